// round 2
// baseline (speedup 1.0000x reference)
#include <cuda_runtime.h>

#define N_SAMP 8192
#define NF 45
#define NE 256
#define EPS 1e-5f

// PERM[k] = original column index, FOFF[k] = field offset into vocab tables
__constant__ int c_perm[NF] = {
    0,1,2,3,4,5,6,7,8,9,
    10,11,12,13,14,15,16,17,18,19,20,21,22,23,
    26,27, 28,29, 24,25,
    30,31,32,33,34,35,36,37,38,39,40,41,42,43,44};
__constant__ int c_foff[NF] = {
    0,300,1300,2300,2800,2950,2962,2993,2993,2993,
    3023,3023,3023,3023,3023,3023,3023,3023,3023,3023,3023,3023,3023,3023,
    3223,3223, 53223,53223, 103223,103223,
    123223,123223,123223,123223,123223,123223,123223,123223,123223,123223,
    123223,123223,123223,123223,123223};

__device__ float g_z1[N_SAMP * 32];      // deep @ l1_w^T (no bias)
__device__ float g_fm[N_SAMP];           // fm_first + fm_second + bias
__device__ float g_part[64 * 1056];      // per-block stats partials
__device__ float g_coef[33];             // w[32], C

// ---------------------------------------------------------------------------
// K1: per-sample FM terms. One warp per sample; lane covers 8 channels
// (c = lane + 32*i). Software-pipelined row gathers.
// ---------------------------------------------------------------------------
__global__ void k1_fm(const int* __restrict__ Xi, const float* __restrict__ Xv,
                      const float* __restrict__ W1, const float* __restrict__ W2,
                      const float* __restrict__ bias)
{
    const int warp = threadIdx.x >> 5;
    const int lane = threadIdx.x & 31;
    const int n = blockIdx.x * 8 + warp;

    // Distribute the 45 (idx, xv) pairs across lanes (2 regs each)
    int   id0 = 0, id1 = 0;
    float xv0 = 0.f, xv1 = 0.f;
    if (lane < NF) {
        int p = c_perm[lane];
        id0 = Xi[n * NF + p] + c_foff[lane];
        xv0 = Xv[n * NF + p];
    }
    if (lane + 32 < NF) {
        int p = c_perm[lane + 32];
        id1 = Xi[n * NF + p] + c_foff[lane + 32];
        xv1 = Xv[n * NF + p];
    }

    float s[8];
#pragma unroll
    for (int i = 0; i < 8; i++) s[i] = 0.f;
    float ssq = 0.f, fm1 = 0.f;

    // pipeline: preload feature 0
    int   iv = __shfl_sync(0xffffffffu, id0, 0);
    float xv = __shfl_sync(0xffffffffu, xv0, 0);
    float w[8], wn[8];
    {
        const float* row = W2 + (size_t)iv * NE;
#pragma unroll
        for (int i = 0; i < 8; i++) w[i] = __ldg(row + lane + 32 * i);
    }
    float w1v = __ldg(W1 + iv);

    for (int f = 0; f < NF; f++) {
        float nxv = 0.f, nw1 = 0.f;
        if (f + 1 < NF) {
            int   ni;
            if (f + 1 < 32) {
                ni  = __shfl_sync(0xffffffffu, id0, f + 1);
                nxv = __shfl_sync(0xffffffffu, xv0, f + 1);
            } else {
                ni  = __shfl_sync(0xffffffffu, id1, f + 1 - 32);
                nxv = __shfl_sync(0xffffffffu, xv1, f + 1 - 32);
            }
            const float* nrow = W2 + (size_t)ni * NE;
#pragma unroll
            for (int i = 0; i < 8; i++) wn[i] = __ldg(nrow + lane + 32 * i);
            nw1 = __ldg(W1 + ni);
        }
        fm1 += w1v * xv;
#pragma unroll
        for (int i = 0; i < 8; i++) {
            float e = w[i] * xv;
            s[i] += e;
            ssq  += e * e;
        }
        if (f + 1 < NF) {
#pragma unroll
            for (int i = 0; i < 8; i++) w[i] = wn[i];
            xv = nxv; w1v = nw1;
        }
    }

    float part = -ssq;
#pragma unroll
    for (int i = 0; i < 8; i++) part += s[i] * s[i];
#pragma unroll
    for (int o = 16; o > 0; o >>= 1) part += __shfl_xor_sync(0xffffffffu, part, o);
    if (lane == 0) g_fm[n] = 0.5f * part + fm1 + bias[0];
}

// ---------------------------------------------------------------------------
// K2: z1[n][k] = sum_{f,c} e[n][f*256+c] * l1_w[k][f*256+c]
// 32 samples per block, 8 warps. Warp w owns output channels 4w..4w+3 for
// ALL 32 samples; lane l owns sample l. e staged in smem (stride 257 ->
// conflict-free). l1_w read as uniform float4 LDG (L2-resident, broadcast).
// ---------------------------------------------------------------------------
__global__ void k2_z1(const int* __restrict__ Xi, const float* __restrict__ Xv,
                      const float* __restrict__ W2, const float* __restrict__ L1W)
{
    __shared__ float sm_e[32 * 257];
    const int tid  = threadIdx.x;
    const int warp = tid >> 5;
    const int lane = tid & 31;
    const int nbase = blockIdx.x * 32;

    float acc0 = 0.f, acc1 = 0.f, acc2 = 0.f, acc3 = 0.f;
    const float* Lr0 = L1W + (size_t)(4 * warp + 0) * (NF * NE);
    const float* Lr1 = L1W + (size_t)(4 * warp + 1) * (NF * NE);
    const float* Lr2 = L1W + (size_t)(4 * warp + 2) * (NF * NE);
    const float* Lr3 = L1W + (size_t)(4 * warp + 3) * (NF * NE);

    for (int f = 0; f < NF; f++) {
        __syncthreads();
        // gather phase: warp w fills samples 4w..4w+3
        const int p   = c_perm[f];
        const int off = c_foff[f];
#pragma unroll
        for (int t = 0; t < 4; t++) {
            int sl = warp * 4 + t;
            int n  = nbase + sl;
            int iv = Xi[n * NF + p] + off;
            float xv = Xv[n * NF + p];
            const float* row = W2 + (size_t)iv * NE;
#pragma unroll
            for (int i = 0; i < 8; i++) {
                int c = lane + 32 * i;
                sm_e[sl * 257 + c] = __ldg(row + c) * xv;
            }
        }
        __syncthreads();

        const float* l0 = Lr0 + f * NE;
        const float* l1 = Lr1 + f * NE;
        const float* l2 = Lr2 + f * NE;
        const float* l3 = Lr3 + f * NE;
        const float* eb = sm_e + lane * 257;
#pragma unroll 8
        for (int c = 0; c < NE; c += 4) {
            float4 a0 = *(const float4*)(l0 + c);
            float4 a1 = *(const float4*)(l1 + c);
            float4 a2 = *(const float4*)(l2 + c);
            float4 a3 = *(const float4*)(l3 + c);
            float e0 = eb[c], e1 = eb[c + 1], e2 = eb[c + 2], e3 = eb[c + 3];
            acc0 += e0 * a0.x + e1 * a0.y + e2 * a0.z + e3 * a0.w;
            acc1 += e0 * a1.x + e1 * a1.y + e2 * a1.z + e3 * a1.w;
            acc2 += e0 * a2.x + e1 * a2.y + e2 * a2.z + e3 * a2.w;
            acc3 += e0 * a3.x + e1 * a3.y + e2 * a3.z + e3 * a3.w;
        }
    }

    const int n = nbase + lane;
    g_z1[n * 32 + 4 * warp + 0] = acc0;
    g_z1[n * 32 + 4 * warp + 1] = acc1;
    g_z1[n * 32 + 4 * warp + 2] = acc2;
    g_z1[n * 32 + 4 * warp + 3] = acc3;
}

// ---------------------------------------------------------------------------
// K3a: per-block partial sums of z1 (mean vector + full 32x32 second moments)
// ---------------------------------------------------------------------------
__global__ void k3a_stats()
{
    __shared__ float sm[128 * 33];
    const int tid  = threadIdx.x;
    const int base = blockIdx.x * 128 * 32;
    for (int idx = tid; idx < 4096; idx += 256) {
        int s = idx >> 5, j = idx & 31;
        sm[s * 33 + j] = g_z1[base + idx];
    }
    __syncthreads();
    float* outp = g_part + blockIdx.x * 1056;
    if (tid < 32) {
        float acc = 0.f;
        for (int s = 0; s < 128; s++) acc += sm[s * 33 + tid];
        outp[tid] = acc;
    }
#pragma unroll
    for (int p4 = 0; p4 < 4; p4++) {
        int p = tid * 4 + p4;
        int i = p >> 5, j = p & 31;
        float acc = 0.f;
        for (int s = 0; s < 128; s++) acc += sm[s * 33 + i] * sm[s * 33 + j];
        outp[32 + p] = acc;
    }
}

// ---------------------------------------------------------------------------
// K3b: reduce partials, solve closed-form batchnorm composition:
//   h.sum = sum_j w_j * z1_j + C
//   a1_j = bn1_g_j * rsqrt(var1_j + eps)
//   v2_k = u_k^T Cov u_k, u_k[j] = l2_w[k][j]*a1_j
//   a2_k = bn2_g_k * rsqrt(v2_k + eps)
//   w_j  = a1_j * sum_k a2_k * l2_w[k][j];  C = sum_k bn2_b_k - sum_j w_j m1_j
// (l1_b, l2_b, bn1_b all cancel inside batchnorm -> exact.)
// ---------------------------------------------------------------------------
__global__ void k3b_coef(const float* __restrict__ bn1_g,
                         const float* __restrict__ l2w,
                         const float* __restrict__ bn2_g,
                         const float* __restrict__ bn2_b)
{
    __shared__ float st[1056];
    __shared__ float cov[1024];
    __shared__ float m1[32], a1[32], a2[32];
    __shared__ float u[1024];
    const int tid = threadIdx.x;

    for (int e = tid; e < 1056; e += 256) {
        float acc = 0.f;
        for (int b = 0; b < 64; b++) acc += g_part[b * 1056 + e];
        st[e] = acc;
    }
    __syncthreads();
    if (tid < 32) m1[tid] = st[tid] * (1.f / 8192.f);
    __syncthreads();
    for (int p = tid; p < 1024; p += 256) {
        int i = p >> 5, j = p & 31;
        cov[p] = st[32 + p] * (1.f / 8192.f) - m1[i] * m1[j];
    }
    __syncthreads();
    if (tid < 32) a1[tid] = bn1_g[tid] * rsqrtf(cov[tid * 33] + EPS);
    __syncthreads();
    for (int p = tid; p < 1024; p += 256) {
        int j = p & 31;
        u[p] = l2w[p] * a1[j];
    }
    __syncthreads();
    if (tid < 32) {
        const int k = tid;
        float v2 = 0.f;
        for (int i = 0; i < 32; i++) {
            float ui = u[k * 32 + i];
            float t = 0.f;
            for (int j = 0; j < 32; j++) t += cov[i * 32 + j] * u[k * 32 + j];
            v2 += ui * t;
        }
        a2[k] = bn2_g[k] * rsqrtf(v2 + EPS);
    }
    __syncthreads();
    if (tid < 32) {
        const int j = tid;
        float q = 0.f;
        for (int k = 0; k < 32; k++) q += a2[k] * l2w[k * 32 + j];
        g_coef[j] = q * a1[j];
    }
    __syncthreads();
    if (tid == 0) {
        float C = 0.f;
        for (int k = 0; k < 32; k++) C += bn2_b[k];
        for (int j = 0; j < 32; j++) C -= g_coef[j] * m1[j];
        g_coef[32] = C;
    }
}

// ---------------------------------------------------------------------------
// K4: out[n] = fm[n] + sum_j w_j * z1[n][j] + C
// ---------------------------------------------------------------------------
__global__ void k4_out(float* __restrict__ out)
{
    __shared__ float w[33];
    if (threadIdx.x < 33) w[threadIdx.x] = g_coef[threadIdx.x];
    __syncthreads();
    const int n = blockIdx.x * 256 + threadIdx.x;
    const float4* z = (const float4*)(g_z1 + n * 32);
    float acc = 0.f;
#pragma unroll
    for (int i = 0; i < 8; i++) {
        float4 v = z[i];
        acc += v.x * w[4 * i] + v.y * w[4 * i + 1] + v.z * w[4 * i + 2] + v.w * w[4 * i + 3];
    }
    out[n] = g_fm[n] + acc + w[32];
}

// ---------------------------------------------------------------------------
extern "C" void kernel_launch(void* const* d_in, const int* in_sizes, int n_in,
                              void* d_out, int out_size)
{
    const int*   Xi    = (const int*)d_in[0];
    const float* Xv    = (const float*)d_in[1];
    const float* W1    = (const float*)d_in[2];
    const float* W2    = (const float*)d_in[3];
    const float* bias  = (const float*)d_in[4];
    const float* l1_w  = (const float*)d_in[5];
    // d_in[6] = l1_b  (cancels in batchnorm)
    const float* bn1_g = (const float*)d_in[7];
    // d_in[8] = bn1_b (cancels)
    const float* l2_w  = (const float*)d_in[9];
    // d_in[10] = l2_b (cancels)
    const float* bn2_g = (const float*)d_in[11];
    const float* bn2_b = (const float*)d_in[12];
    float* out = (float*)d_out;

    k1_fm<<<N_SAMP / 8, 256>>>(Xi, Xv, W1, W2, bias);
    k2_z1<<<N_SAMP / 32, 256>>>(Xi, Xv, W2, l1_w);
    k3a_stats<<<64, 256>>>();
    k3b_coef<<<1, 256>>>(bn1_g, l2_w, bn2_g, bn2_b);
    k4_out<<<N_SAMP / 256, 256>>>(out);
}

// round 3
// speedup vs baseline: 1.3506x; 1.3506x over previous
#include <cuda_runtime.h>
#include <cstring>

#define NF 45
#define NE 256
#define N_SAMP 8192
#define EPS 1e-5f
#define L1STRIDE 11520   // 45*256

// PERM[k] = original column index, FOFF[k] = field offset into vocab tables
__constant__ int c_perm[NF] = {
    0,1,2,3,4,5,6,7,8,9,
    10,11,12,13,14,15,16,17,18,19,20,21,22,23,
    26,27, 28,29, 24,25,
    30,31,32,33,34,35,36,37,38,39,40,41,42,43,44};
__constant__ int c_foff[NF] = {
    0,300,1300,2300,2800,2950,2962,2993,2993,2993,
    3023,3023,3023,3023,3023,3023,3023,3023,3023,3023,3023,3023,3023,3023,
    3223,3223, 53223,53223, 103223,103223,
    123223,123223,123223,123223,123223,123223,123223,123223,123223,123223,
    123223,123223,123223,123223,123223};
// small-column (f<24) vocab sizes and cumulative bases into the T table
__constant__ int c_vsize[24] = {300,1000,1000,500,150,12,31,30,30,30,
    200,200,200,200,200,200,200,200,200,200,200,200,200,200};
__constant__ int c_cbase[24] = {0,300,1300,2300,2800,2950,2962,2993,3023,3053,
    3083,3283,3483,3683,3883,4083,4283,4483,4683,4883,5083,5283,5483,5683};
#define T_ROWS 5883

__device__ float g_T[T_ROWS * 32];       // small-col table: T[row][k]
__device__ float g_z1[N_SAMP * 32];      // deep @ l1_w^T (no bias)
__device__ float g_fm[N_SAMP];           // fm_first + fm_second + bias
__device__ float g_part[16 * 1056];      // per-block stats partials
__device__ float g_coef[33];             // w[32], C

#define FMA2(acc, a, b) \
    asm("fma.rn.f32x2 %0, %1, %2, %0;" : "+l"(acc) : "l"(a), "l"(b))

// ---------------------------------------------------------------------------
// K0: table T[cbase[f]+v][k] = dot256(W2[foff[f]+v], l1_w[k, f*256:(f+1)*256])
// Block: 8 vocab rows x 32 channels = 256 threads. l1_w slice staged in smem.
// ---------------------------------------------------------------------------
__global__ void k0_table(const float* __restrict__ W2, const float* __restrict__ L1W)
{
    __shared__ float lw[32 * 257];
    const int tid = threadIdx.x;

    int b = blockIdx.x, f = 0;
    for (f = 0; f < 24; f++) {
        int nb = (c_vsize[f] + 7) >> 3;
        if (b < nb) break;
        b -= nb;
    }
    const int v0 = b * 8;

    for (int idx = tid; idx < 8192; idx += 256) {
        int k = idx >> 8, c = idx & 255;
        lw[k * 257 + c] = __ldg(L1W + (size_t)k * L1STRIDE + f * NE + c);
    }
    __syncthreads();

    const int v = v0 + (tid >> 5);
    const int k = tid & 31;
    if (v < c_vsize[f]) {
        const float* w2r = W2 + (size_t)(c_foff[f] + v) * NE;
        float a0 = 0.f, a1 = 0.f, a2 = 0.f, a3 = 0.f;
#pragma unroll 4
        for (int c = 0; c < NE; c += 4) {
            float4 w = __ldg((const float4*)(w2r + c));
            a0 += w.x * lw[k * 257 + c];
            a1 += w.y * lw[k * 257 + c + 1];
            a2 += w.z * lw[k * 257 + c + 2];
            a3 += w.w * lw[k * 257 + c + 3];
        }
        g_T[(size_t)(c_cbase[f] + v) * 32 + k] = (a0 + a1) + (a2 + a3);
    }
}

// ---------------------------------------------------------------------------
// K1: per-sample FM terms. One warp per sample; lane owns channels
// [4l,4l+4) and [128+4l,128+4l+4) -> two LDG.128 per row.
// ---------------------------------------------------------------------------
__global__ void k1_fm(const int* __restrict__ Xi, const float* __restrict__ Xv,
                      const float* __restrict__ W1, const float* __restrict__ W2,
                      const float* __restrict__ bias)
{
    const int warp = threadIdx.x >> 5;
    const int lane = threadIdx.x & 31;
    const int n = blockIdx.x * 8 + warp;

    int   id0 = 0, id1 = 0;
    float xv0 = 0.f, xv1 = 0.f;
    if (lane < NF) {
        int p = c_perm[lane];
        id0 = __ldg(Xi + n * NF + p) + c_foff[lane];
        xv0 = __ldg(Xv + n * NF + p);
    }
    if (lane + 32 < NF) {
        int p = c_perm[lane + 32];
        id1 = __ldg(Xi + n * NF + p) + c_foff[lane + 32];
        xv1 = __ldg(Xv + n * NF + p);
    }

    float4 s0 = make_float4(0.f, 0.f, 0.f, 0.f);
    float4 s1 = make_float4(0.f, 0.f, 0.f, 0.f);
    float ssq = 0.f, fm1 = 0.f;

    int   iv = __shfl_sync(0xffffffffu, id0, 0);
    float xv = __shfl_sync(0xffffffffu, xv0, 0);
    const float* row = W2 + (size_t)iv * NE;
    float4 wa = __ldg((const float4*)(row + 4 * lane));
    float4 wb = __ldg((const float4*)(row + 4 * lane + 128));
    float w1v = __ldg(W1 + iv);

    for (int f = 0; f < NF; f++) {
        float4 na = make_float4(0.f, 0.f, 0.f, 0.f);
        float4 nb = make_float4(0.f, 0.f, 0.f, 0.f);
        float nxv = 0.f, nw1 = 0.f;
        if (f + 1 < NF) {
            int ni;
            if (f + 1 < 32) {
                ni  = __shfl_sync(0xffffffffu, id0, f + 1);
                nxv = __shfl_sync(0xffffffffu, xv0, f + 1);
            } else {
                ni  = __shfl_sync(0xffffffffu, id1, f - 31);
                nxv = __shfl_sync(0xffffffffu, xv1, f - 31);
            }
            const float* r2 = W2 + (size_t)ni * NE;
            na = __ldg((const float4*)(r2 + 4 * lane));
            nb = __ldg((const float4*)(r2 + 4 * lane + 128));
            nw1 = __ldg(W1 + ni);
        }
        fm1 += w1v * xv;
        float ex;
        ex = wa.x * xv; s0.x += ex; ssq += ex * ex;
        ex = wa.y * xv; s0.y += ex; ssq += ex * ex;
        ex = wa.z * xv; s0.z += ex; ssq += ex * ex;
        ex = wa.w * xv; s0.w += ex; ssq += ex * ex;
        ex = wb.x * xv; s1.x += ex; ssq += ex * ex;
        ex = wb.y * xv; s1.y += ex; ssq += ex * ex;
        ex = wb.z * xv; s1.z += ex; ssq += ex * ex;
        ex = wb.w * xv; s1.w += ex; ssq += ex * ex;
        wa = na; wb = nb; xv = nxv; w1v = nw1;
    }

    float part = s0.x * s0.x + s0.y * s0.y + s0.z * s0.z + s0.w * s0.w
               + s1.x * s1.x + s1.y * s1.y + s1.z * s1.z + s1.w * s1.w - ssq;
#pragma unroll
    for (int o = 16; o > 0; o >>= 1) part += __shfl_xor_sync(0xffffffffu, part, o);
    if (lane == 0) g_fm[n] = 0.5f * part + fm1 + bias[0];
}

// ---------------------------------------------------------------------------
// K2: z1. 64 samples/block, 256 threads. Warp owns 4 output channels, lane
// owns samples (lane, lane+32). Small cols via table T; large cols via
// double-buffered smem e + packed f32x2 GEMM.
// ---------------------------------------------------------------------------
#define ESTRIDE 260
#define K2_SMEM (2 * 64 * ESTRIDE * 4)

__device__ __forceinline__ void k2_gather(int f, float* buf,
                                          const int* __restrict__ Xi,
                                          const float* __restrict__ Xv,
                                          const float* __restrict__ W2,
                                          int nbase, int warp, int lane)
{
    const int p = c_perm[f];
    const int off = c_foff[f];
#pragma unroll 4
    for (int t = 0; t < 8; t++) {
        const int s = warp * 8 + t;
        const int n = nbase + s;
        const int iv = __ldg(Xi + n * NF + p) + off;
        const float xv = __ldg(Xv + n * NF + p);
        const float* row = W2 + (size_t)iv * NE;
        float4 a = __ldg((const float4*)(row + 4 * lane));
        float4 b = __ldg((const float4*)(row + 4 * lane + 128));
        float* d = buf + s * ESTRIDE + 4 * lane;
        *(float4*)d         = make_float4(a.x * xv, a.y * xv, a.z * xv, a.w * xv);
        *(float4*)(d + 128) = make_float4(b.x * xv, b.y * xv, b.z * xv, b.w * xv);
    }
}

__global__ void __launch_bounds__(256)
k2_z1(const int* __restrict__ Xi, const float* __restrict__ Xv,
      const float* __restrict__ W2, const float* __restrict__ L1W)
{
    extern __shared__ float smem[];
    float* bufA = smem;
    float* bufB = smem + 64 * ESTRIDE;

    const int tid = threadIdx.x;
    const int warp = tid >> 5;
    const int lane = tid & 31;
    const int nbase = blockIdx.x * 64;

    // ---- small columns: table lookups
    float tac[8];
#pragma unroll
    for (int i = 0; i < 8; i++) tac[i] = 0.f;
    const int n0 = nbase + lane, n1 = n0 + 32;
#pragma unroll 4
    for (int f = 0; f < 24; f++) {
        const int p = c_perm[f];
        int   iv0 = __ldg(Xi + n0 * NF + p);
        float x0  = __ldg(Xv + n0 * NF + p);
        int   iv1 = __ldg(Xi + n1 * NF + p);
        float x1  = __ldg(Xv + n1 * NF + p);
        float4 t0 = __ldg((const float4*)(g_T + (size_t)(c_cbase[f] + iv0) * 32 + 4 * warp));
        float4 t1 = __ldg((const float4*)(g_T + (size_t)(c_cbase[f] + iv1) * 32 + 4 * warp));
        tac[0] += x0 * t0.x; tac[1] += x0 * t0.y; tac[2] += x0 * t0.z; tac[3] += x0 * t0.w;
        tac[4] += x1 * t1.x; tac[5] += x1 * t1.y; tac[6] += x1 * t1.z; tac[7] += x1 * t1.w;
    }

    // ---- large columns: double-buffered GEMM
    unsigned long long acc[8];
#pragma unroll
    for (int i = 0; i < 8; i++) acc[i] = 0ull;

    k2_gather(24, bufA, Xi, Xv, W2, nbase, warp, lane);

    for (int fi = 0; fi < 21; fi++) {
        __syncthreads();
        float* cur = (fi & 1) ? bufB : bufA;
        float* nxt = (fi & 1) ? bufA : bufB;
        if (fi < 20) k2_gather(25 + fi, nxt, Xi, Xv, W2, nbase, warp, lane);

        const int f = 24 + fi;
        const float* L0 = L1W + (size_t)(4 * warp) * L1STRIDE + f * NE;
        const float* L1p = L0 + L1STRIDE;
        const float* L2p = L0 + 2 * L1STRIDE;
        const float* L3p = L0 + 3 * L1STRIDE;
        const float* r0 = cur + lane * ESTRIDE;
        const float* r1 = cur + (lane + 32) * ESTRIDE;

#pragma unroll 2
        for (int c = 0; c < NE; c += 4) {
            ulonglong2 w0 = __ldg((const ulonglong2*)(L0 + c));
            ulonglong2 w1 = __ldg((const ulonglong2*)(L1p + c));
            ulonglong2 w2 = __ldg((const ulonglong2*)(L2p + c));
            ulonglong2 w3 = __ldg((const ulonglong2*)(L3p + c));
            ulonglong2 e0 = *(const ulonglong2*)(r0 + c);
            ulonglong2 e1 = *(const ulonglong2*)(r1 + c);
            FMA2(acc[0], e0.x, w0.x); FMA2(acc[0], e0.y, w0.y);
            FMA2(acc[1], e0.x, w1.x); FMA2(acc[1], e0.y, w1.y);
            FMA2(acc[2], e0.x, w2.x); FMA2(acc[2], e0.y, w2.y);
            FMA2(acc[3], e0.x, w3.x); FMA2(acc[3], e0.y, w3.y);
            FMA2(acc[4], e1.x, w0.x); FMA2(acc[4], e1.y, w0.y);
            FMA2(acc[5], e1.x, w1.x); FMA2(acc[5], e1.y, w1.y);
            FMA2(acc[6], e1.x, w2.x); FMA2(acc[6], e1.y, w2.y);
            FMA2(acc[7], e1.x, w3.x); FMA2(acc[7], e1.y, w3.y);
        }
    }

#pragma unroll
    for (int q = 0; q < 2; q++)
#pragma unroll
        for (int j = 0; j < 4; j++) {
            unsigned long long v = acc[q * 4 + j];
            float z = __uint_as_float((unsigned)v) + __uint_as_float((unsigned)(v >> 32))
                    + tac[q * 4 + j];
            g_z1[(size_t)(nbase + lane + 32 * q) * 32 + 4 * warp + j] = z;
        }
}

// ---------------------------------------------------------------------------
// K3a: 16 blocks x 512 samples (4 tiles of 128): mean + 32x32 second moments
// ---------------------------------------------------------------------------
__global__ void k3a_stats()
{
    __shared__ float sm[128 * 33];
    const int tid = threadIdx.x;
    float macc = 0.f;
    float pacc0 = 0.f, pacc1 = 0.f, pacc2 = 0.f, pacc3 = 0.f;
    const int p = tid * 4;
    const int i0 = p >> 5, j0 = p & 31;

    for (int tile = 0; tile < 4; tile++) {
        const int base = blockIdx.x * 512 * 32 + tile * 128 * 32;
        __syncthreads();
        for (int idx = tid; idx < 4096; idx += 256)
            sm[(idx >> 5) * 33 + (idx & 31)] = g_z1[base + idx];
        __syncthreads();
        if (tid < 32) {
            float a = 0.f;
            for (int s = 0; s < 128; s++) a += sm[s * 33 + tid];
            macc += a;
        }
#pragma unroll 4
        for (int s = 0; s < 128; s++) {
            float zi = sm[s * 33 + i0];
            pacc0 += zi * sm[s * 33 + j0];
            pacc1 += zi * sm[s * 33 + j0 + 1];
            pacc2 += zi * sm[s * 33 + j0 + 2];
            pacc3 += zi * sm[s * 33 + j0 + 3];
        }
    }
    float* outp = g_part + blockIdx.x * 1056;
    if (tid < 32) outp[tid] = macc;
    outp[32 + p] = pacc0;
    outp[32 + p + 1] = pacc1;
    outp[32 + p + 2] = pacc2;
    outp[32 + p + 3] = pacc3;
}

// ---------------------------------------------------------------------------
// K3b: reduce partials + closed-form batchnorm composition coefficients
// ---------------------------------------------------------------------------
__global__ void k3b_coef(const float* __restrict__ bn1_g,
                         const float* __restrict__ l2w,
                         const float* __restrict__ bn2_g,
                         const float* __restrict__ bn2_b)
{
    __shared__ float st[1056];
    __shared__ float cov[1024];
    __shared__ float m1[32], a1[32], a2[32];
    __shared__ float u[1024];
    __shared__ float v2s[256];
    const int tid = threadIdx.x;

    for (int e = tid; e < 1056; e += 256) {
        float a = 0.f;
#pragma unroll
        for (int b = 0; b < 16; b++) a += g_part[b * 1056 + e];
        st[e] = a;
    }
    __syncthreads();
    if (tid < 32) m1[tid] = st[tid] * (1.f / 8192.f);
    __syncthreads();
    for (int q = tid; q < 1024; q += 256) {
        int i = q >> 5, j = q & 31;
        cov[q] = st[32 + q] * (1.f / 8192.f) - m1[i] * m1[j];
    }
    __syncthreads();
    if (tid < 32) a1[tid] = bn1_g[tid] * rsqrtf(cov[tid * 33] + EPS);
    __syncthreads();
    for (int q = tid; q < 1024; q += 256) {
        int j = q & 31;
        u[q] = l2w[q] * a1[j];
    }
    __syncthreads();
    {
        const int k = tid & 31, seg = tid >> 5;
        float pv = 0.f;
#pragma unroll
        for (int i = seg * 4; i < seg * 4 + 4; i++) {
            float t = 0.f;
#pragma unroll
            for (int j = 0; j < 32; j++) t += cov[i * 32 + j] * u[k * 32 + j];
            pv += u[k * 32 + i] * t;
        }
        v2s[seg * 32 + k] = pv;
    }
    __syncthreads();
    if (tid < 32) {
        float v2 = 0.f;
#pragma unroll
        for (int s = 0; s < 8; s++) v2 += v2s[s * 32 + tid];
        a2[tid] = bn2_g[tid] * rsqrtf(v2 + EPS);
    }
    __syncthreads();
    if (tid < 32) {
        const int j = tid;
        float q = 0.f;
#pragma unroll
        for (int k = 0; k < 32; k++) q += a2[k] * l2w[k * 32 + j];
        g_coef[j] = q * a1[j];
    }
    __syncthreads();
    if (tid == 0) {
        float C = 0.f;
        for (int k = 0; k < 32; k++) C += bn2_b[k];
        for (int j = 0; j < 32; j++) C -= g_coef[j] * m1[j];
        g_coef[32] = C;
    }
}

// ---------------------------------------------------------------------------
// K4: out[n] = fm[n] + sum_j w_j * z1[n][j] + C
// ---------------------------------------------------------------------------
__global__ void k4_out(float* __restrict__ out)
{
    __shared__ float w[33];
    if (threadIdx.x < 33) w[threadIdx.x] = g_coef[threadIdx.x];
    __syncthreads();
    const int n = blockIdx.x * 256 + threadIdx.x;
    const float4* z = (const float4*)(g_z1 + (size_t)n * 32);
    float acc = 0.f;
#pragma unroll
    for (int i = 0; i < 8; i++) {
        float4 v = z[i];
        acc += v.x * w[4 * i] + v.y * w[4 * i + 1] + v.z * w[4 * i + 2] + v.w * w[4 * i + 3];
    }
    out[n] = g_fm[n] + acc + w[32];
}

// ---------------------------------------------------------------------------
extern "C" void kernel_launch(void* const* d_in, const int* in_sizes, int n_in,
                              void* d_out, int out_size)
{
    const int*   Xi    = (const int*)d_in[0];
    const float* Xv    = (const float*)d_in[1];
    const float* W1    = (const float*)d_in[2];
    const float* W2    = (const float*)d_in[3];
    const float* bias  = (const float*)d_in[4];
    const float* l1_w  = (const float*)d_in[5];
    const float* bn1_g = (const float*)d_in[7];
    const float* l2_w  = (const float*)d_in[9];
    const float* bn2_g = (const float*)d_in[11];
    const float* bn2_b = (const float*)d_in[12];
    float* out = (float*)d_out;

    cudaFuncSetAttribute(k2_z1, cudaFuncAttributeMaxDynamicSharedMemorySize, K2_SMEM);

    k0_table<<<738, 256>>>(W2, l1_w);
    k1_fm<<<N_SAMP / 8, 256>>>(Xi, Xv, W1, W2, bias);
    k2_z1<<<N_SAMP / 64, 256, K2_SMEM>>>(Xi, Xv, W2, l1_w);
    k3a_stats<<<16, 256>>>();
    k3b_coef<<<1, 256>>>(bn1_g, l2_w, bn2_g, bn2_b);
    k4_out<<<N_SAMP / 256, 256>>>(out);
}